// round 1
// baseline (speedup 1.0000x reference)
#include <cuda_runtime.h>
#include <cstdint>

typedef unsigned long long ULL;

// Flag table: g_tab[jb*64 + lt] = uint4; word c holds bytes m=0..3 for
// pair (i = 4*lt + c, j = 4*jb + m): bit0 = sign negative, bit1 = wedge, bit2 = inner.
__device__ uint4 g_tab[4096];

__global__ void build_tab_kernel() {
    int idx = blockIdx.x * blockDim.x + threadIdx.x;
    if (idx >= 4096) return;
    int lt = idx & 63;
    int jb = idx >> 6;
    unsigned w[4];
#pragma unroll
    for (int c = 0; c < 4; c++) {
        int i = 4 * lt + c;
        unsigned word = 0;
#pragma unroll
        for (int m = 0; m < 4; m++) {
            int j = 4 * jb + m;
            int k = i ^ j;
            int par = 0;
#pragma unroll
            for (int p = 0; p < 8; p++)
                if ((j >> p) & 1) par ^= __popc(k & ((1 << p) - 1)) & 1;
            int gi = __popc(i), gj = __popc(j), gk = __popc(k);
            unsigned b = (unsigned)par;             // bit0: sign
            if (gi == gj + gk) b |= 2u;             // bit1: wedge
            int d = gj - gk; if (d < 0) d = -d;
            if (gi == d) b |= 4u;                   // bit2: inner
            word |= b << (8 * m);
        }
        w[c] = word;
    }
    g_tab[idx] = make_uint4(w[0], w[1], w[2], w[3]);
}

__device__ __forceinline__ ULL mul2(ULL a, ULL b) {
    ULL d;
    asm("mul.rn.f32x2 %0, %1, %2;" : "=l"(d) : "l"(a), "l"(b));
    return d;
}
__device__ __forceinline__ ULL add2(ULL a, ULL b) {
    ULL d;
    asm("add.rn.f32x2 %0, %1, %2;" : "=l"(d) : "l"(a), "l"(b));
    return d;
}
__device__ __forceinline__ void padd2(ULL& acc, ULL v, unsigned cond) {
    asm("{\n\t.reg .pred p;\n\tsetp.ne.u32 p, %2, 0;\n\t@p add.rn.f32x2 %0, %0, %1;\n\t}"
        : "+l"(acc) : "l"(v), "r"(cond));
}
__device__ __forceinline__ float lof(ULL x) { return __uint_as_float((unsigned)x); }
__device__ __forceinline__ float hif(ULL x) { return __uint_as_float((unsigned)(x >> 32)); }

// One block (64 threads) handles 2 positions packed in f32x2.
// Thread lt handles outputs i = 4*lt .. 4*lt+3 for both positions.
__global__ void __launch_bounds__(64) clifford_main_kernel(
    const float* __restrict__ A, const float* __restrict__ B, float* __restrict__ out)
{
    __shared__ __align__(16) float As[512];   // [j][pos], pos-interleaved f32x2 packs
    __shared__ __align__(16) float Bs[512];   // same, XOR-swizzled at 16B granularity

    const int lt = threadIdx.x;               // 0..63
    const int p0 = blockIdx.x * 2;            // first of 2 positions
    const float* A0 = A + (size_t)p0 * 256;
    const float* B0 = B + (size_t)p0 * 256;

    // Fill shared: As[2n..] = {A[p0][n], A[p0+1][n]}; Bs swizzled.
    for (int n = lt; n < 256; n += 64) {
        As[2 * n]     = A0[n];
        As[2 * n + 1] = A0[n + 256];
        int u  = n >> 1;                      // 16B unit index (holds k = 2u, 2u+1)
        int s  = u ^ ((u >> 3) & 1);          // bank swizzle
        int bi = s * 4 + (n & 1) * 2;
        Bs[bi]     = B0[n];
        Bs[bi + 1] = B0[n + 256];
    }
    __syncthreads();

    ULL gp[4]  = {0ull, 0ull, 0ull, 0ull};
    ULL we[4]  = {0ull, 0ull, 0ull, 0ull};
    ULL inn[4] = {0ull, 0ull, 0ull, 0ull};

    const ulonglong2* Asu = (const ulonglong2*)As;
    const ulonglong2* Bsu = (const ulonglong2*)Bs;

#pragma unroll 2
    for (int jb = 0; jb < 64; jb++) {
        const uint4 q = __ldg(&g_tab[jb * 64 + lt]);   // one coalesced LDG.128
        unsigned wq[4] = {q.x, q.y, q.z, q.w};

        // A packs for j = 4jb..4jb+3 (uniform broadcast LDS.128 x2)
        ulonglong2 aL = Asu[2 * jb];
        ulonglong2 aH = Asu[2 * jb + 1];
        ULL a2[4] = {aL.x, aL.y, aH.x, aH.y};

        // B packs for k = 4(lt^jb) .. +3, through the swizzle
        int x   = lt ^ jb;
        int b3  = (x >> 2) & 1;
        int sLo = (2 * x) ^ b3;
        int sHi = (2 * x + 1) ^ b3;
        ulonglong2 bL = Bsu[sLo];
        ulonglong2 bH = Bsu[sHi];
        ULL b2[4] = {bL.x, bL.y, bH.x, bH.y};

#pragma unroll
        for (int c = 0; c < 4; c++) {
            const unsigned w = wq[c];
#pragma unroll
            for (int m = 0; m < 4; m++) {
                ULL p = mul2(a2[m], b2[c ^ m]);
                // apply sign (bit 8m) to both packed halves
                unsigned msk = (w << (31 - 8 * m)) & 0x80000000u;
                unsigned lo = (unsigned)p ^ msk;
                unsigned hi = (unsigned)(p >> 32) ^ msk;
                p = (ULL)lo | ((ULL)hi << 32);
                gp[c] = add2(gp[c], p);
                padd2(we[c],  p, w & (2u << (8 * m)));
                padd2(inn[c], p, w & (4u << (8 * m)));
            }
        }
    }

    // Write out: out[prod][pos][i], i = 4lt..4lt+3 as float4.
    float4* o4 = (float4*)out;
    // pos 0 (low halves)
    {
        size_t base = (size_t)(p0) * 64 + lt;
        o4[base + 0 * 1024 * 64] = make_float4(lof(gp[0]),  lof(gp[1]),  lof(gp[2]),  lof(gp[3]));
        o4[base + 1 * 1024 * 64] = make_float4(lof(we[0]),  lof(we[1]),  lof(we[2]),  lof(we[3]));
        o4[base + 2 * 1024 * 64] = make_float4(lof(inn[0]), lof(inn[1]), lof(inn[2]), lof(inn[3]));
    }
    // pos 1 (high halves)
    {
        size_t base = (size_t)(p0 + 1) * 64 + lt;
        o4[base + 0 * 1024 * 64] = make_float4(hif(gp[0]),  hif(gp[1]),  hif(gp[2]),  hif(gp[3]));
        o4[base + 1 * 1024 * 64] = make_float4(hif(we[0]),  hif(we[1]),  hif(we[2]),  hif(we[3]));
        o4[base + 2 * 1024 * 64] = make_float4(hif(inn[0]), hif(inn[1]), hif(inn[2]), hif(inn[3]));
    }
}

extern "C" void kernel_launch(void* const* d_in, const int* in_sizes, int n_in,
                              void* d_out, int out_size) {
    const float* A = (const float*)d_in[0];
    const float* B = (const float*)d_in[1];
    float* out = (float*)d_out;

    // Rebuild flag table every call (deterministic, idempotent, capture-safe).
    build_tab_kernel<<<16, 256>>>();

    // 1024 positions / 2 per block = 512 blocks of 64 threads.
    clifford_main_kernel<<<512, 64>>>(A, B, out);
}

// round 14
// speedup vs baseline: 1.4266x; 1.4266x over previous
#include <cuda_runtime.h>
#include <cstdint>

typedef unsigned long long ULL;

// Per-(jb,lt) outer flags:
// bit0: S   = sign(jb, lt^jb) negative
// bit1: W   = jb subset-of lt            (wedge outer)
// bit2: I1  = (lt & jb)==0               (j subset k outer)
// bit3: I2  = lt subset-of jb            (k subset j outer)
// bit4: Ior = I1 | I2
// bit5: P   = popc(jb) & 1               (parity cross-term)
__device__ unsigned g_flags[4096];

__global__ void build_flags_kernel() {
    int idx = blockIdx.x * blockDim.x + threadIdx.x;
    if (idx >= 4096) return;
    int lt = idx & 63;
    int jb = idx >> 6;
    int kh = lt ^ jb;
    int par = 0;
#pragma unroll
    for (int p = 0; p < 6; p++)
        if ((jb >> p) & 1) par ^= __popc(kh & ((1 << p) - 1)) & 1;
    unsigned f = (unsigned)par;
    if ((jb & ~lt) == 0) f |= 2u;    // W : jb subset lt
    if ((lt & jb) == 0)  f |= 4u;    // I1
    if ((lt & ~jb) == 0) f |= 8u;    // I2
    if (f & 12u)         f |= 16u;   // Ior
    if (__popc(jb) & 1)  f |= 32u;   // P  (bit the R3 rewrite dropped)
    g_flags[idx] = f;
}

__device__ __forceinline__ float lof(ULL x) { return __uint_as_float((unsigned)x); }
__device__ __forceinline__ float hif(ULL x) { return __uint_as_float((unsigned)(x >> 32)); }

// 256 threads: 4 "quads" of 64 threads.
// quad h handles jb in [16h, 16h+16); lt = tid & 63 handles outputs i=4lt..4lt+3
// for 2 positions packed as f32x2.
__global__ void __launch_bounds__(256) clifford_main_kernel(
    const float* __restrict__ A, const float* __restrict__ B, float* __restrict__ out)
{
    __shared__ __align__(16) float As[512];
    __shared__ __align__(16) float Bs[512];
    __shared__ __align__(16) unsigned Fs[4096];   // flags staged per block
    __shared__ ULL red[36][64];                   // 3 quads x 12 accumulators

    const int tid = threadIdx.x;
    const int lt  = tid & 63;
    const int h   = tid >> 6;
    const int p0  = blockIdx.x * 2;
    const float* A0 = A + (size_t)p0 * 256;
    const float* B0 = B + (size_t)p0 * 256;

    // Stage A (plain) and B (16B-XOR-swizzled) into shared, pos-pair interleaved.
    {
        int n = tid;                           // 0..255
        As[2 * n]     = A0[n];
        As[2 * n + 1] = A0[n + 256];
        int u  = n >> 1;
        int s  = u ^ ((u >> 3) & 1);
        int bi = s * 4 + (n & 1) * 2;
        Bs[bi]     = B0[n];
        Bs[bi + 1] = B0[n + 256];
    }
    // Stage flags: 4096 words via coalesced uint4 loads.
    {
        const uint4* src = (const uint4*)g_flags;
        uint4* dst = (uint4*)Fs;
#pragma unroll
        for (int r = 0; r < 4; r++)
            dst[r * 256 + tid] = src[r * 256 + tid];
    }
    __syncthreads();

    ULL gp[4] = {0,0,0,0}, we[4] = {0,0,0,0}, in_[4] = {0,0,0,0};

    const ulonglong2* Asu = (const ulonglong2*)As;
    const ulonglong2* Bsu = (const ulonglong2*)Bs;

#pragma unroll 4
    for (int q = 0; q < 16; q++) {
        const int jb = h * 16 + q;
        const unsigned f = Fs[jb * 64 + lt];

        // A packs for j = 4jb..4jb+3 (uniform broadcast)
        ulonglong2 aL = Asu[2 * jb];
        ulonglong2 aH = Asu[2 * jb + 1];
        ULL a0 = aL.x, a1 = aL.y, a2_ = aH.x, a3 = aH.y;

        // B packs for kL = 0..3 at kH = lt^jb, through the swizzle
        int x   = lt ^ jb;
        int b3s = (x >> 2) & 1;
        ulonglong2 bL = Bsu[(2 * x) ^ b3s];
        ulonglong2 bH = Bsu[(2 * x + 1) ^ b3s];
        ULL b0 = bL.x, b1 = bL.y, b2_ = bH.x, b3 = bH.y;

        // Outer sign S on all packs; parity cross-term P flips kL in {1,2}.
        unsigned m03 = f << 31;                          // bit0 (S) -> sign bit
        unsigned m12 = m03 ^ ((f << 26) & 0x80000000u);  // ^ bit5 (P)
        ULL mm03 = ((ULL)m03 << 32) | m03;
        ULL mm12 = ((ULL)m12 << 32) | m12;
        b0 ^= mm03; b3 ^= mm03;
        b1 ^= mm12; b2_ ^= mm12;

        // 16 pairs; compile-time inner sign via add/sub; shared predicates.
        asm(
        "{\n\t"
        ".reg .pred pw, p1, p2, po;\n\t"
        ".reg .b32 tf;\n\t"
        ".reg .b64 t0, t1, t2, t3;\n\t"
        "and.b32 tf, %20, 2;  setp.ne.u32 pw, tf, 0;\n\t"
        "and.b32 tf, %20, 4;  setp.ne.u32 p1, tf, 0;\n\t"
        "and.b32 tf, %20, 8;  setp.ne.u32 p2, tf, 0;\n\t"
        "and.b32 tf, %20, 16; setp.ne.u32 po, tf, 0;\n\t"
        // c0,m0,n0: +, W, Ior
        "mul.rn.f32x2 t0, %12, %16;\n\t"
        "add.rn.f32x2 %0, %0, t0;\n\t"
        "@pw add.rn.f32x2 %4, %4, t0;\n\t"
        "@po add.rn.f32x2 %8, %8, t0;\n\t"
        // c0,m1,n1: +, Ior
        "mul.rn.f32x2 t1, %13, %17;\n\t"
        "add.rn.f32x2 %0, %0, t1;\n\t"
        "@po add.rn.f32x2 %8, %8, t1;\n\t"
        // c0,m2,n2: +, Ior
        "mul.rn.f32x2 t2, %14, %18;\n\t"
        "add.rn.f32x2 %0, %0, t2;\n\t"
        "@po add.rn.f32x2 %8, %8, t2;\n\t"
        // c0,m3,n3: -, Ior
        "mul.rn.f32x2 t3, %15, %19;\n\t"
        "sub.rn.f32x2 %0, %0, t3;\n\t"
        "@po sub.rn.f32x2 %8, %8, t3;\n\t"
        // c1,m0,n1: +, W, p1
        "mul.rn.f32x2 t0, %12, %17;\n\t"
        "add.rn.f32x2 %1, %1, t0;\n\t"
        "@pw add.rn.f32x2 %5, %5, t0;\n\t"
        "@p1 add.rn.f32x2 %9, %9, t0;\n\t"
        // c1,m1,n0: +, W, p2
        "mul.rn.f32x2 t1, %13, %16;\n\t"
        "add.rn.f32x2 %1, %1, t1;\n\t"
        "@pw add.rn.f32x2 %5, %5, t1;\n\t"
        "@p2 add.rn.f32x2 %9, %9, t1;\n\t"
        // c1,m2,n3: -, p1
        "mul.rn.f32x2 t2, %14, %19;\n\t"
        "sub.rn.f32x2 %1, %1, t2;\n\t"
        "@p1 sub.rn.f32x2 %9, %9, t2;\n\t"
        // c1,m3,n2: +, p2
        "mul.rn.f32x2 t3, %15, %18;\n\t"
        "add.rn.f32x2 %1, %1, t3;\n\t"
        "@p2 add.rn.f32x2 %9, %9, t3;\n\t"
        // c2,m0,n2: +, W, p1
        "mul.rn.f32x2 t0, %12, %18;\n\t"
        "add.rn.f32x2 %2, %2, t0;\n\t"
        "@pw add.rn.f32x2 %6, %6, t0;\n\t"
        "@p1 add.rn.f32x2 %10, %10, t0;\n\t"
        // c2,m1,n3: +, p1
        "mul.rn.f32x2 t1, %13, %19;\n\t"
        "add.rn.f32x2 %2, %2, t1;\n\t"
        "@p1 add.rn.f32x2 %10, %10, t1;\n\t"
        // c2,m2,n0: +, W, p2
        "mul.rn.f32x2 t2, %14, %16;\n\t"
        "add.rn.f32x2 %2, %2, t2;\n\t"
        "@pw add.rn.f32x2 %6, %6, t2;\n\t"
        "@p2 add.rn.f32x2 %10, %10, t2;\n\t"
        // c2,m3,n1: -, p2
        "mul.rn.f32x2 t3, %15, %17;\n\t"
        "sub.rn.f32x2 %2, %2, t3;\n\t"
        "@p2 sub.rn.f32x2 %10, %10, t3;\n\t"
        // c3,m0,n3: +, W, p1
        "mul.rn.f32x2 t0, %12, %19;\n\t"
        "add.rn.f32x2 %3, %3, t0;\n\t"
        "@pw add.rn.f32x2 %7, %7, t0;\n\t"
        "@p1 add.rn.f32x2 %11, %11, t0;\n\t"
        // c3,m1,n2: +, W
        "mul.rn.f32x2 t1, %13, %18;\n\t"
        "add.rn.f32x2 %3, %3, t1;\n\t"
        "@pw add.rn.f32x2 %7, %7, t1;\n\t"
        // c3,m2,n1: -, W
        "mul.rn.f32x2 t2, %14, %17;\n\t"
        "sub.rn.f32x2 %3, %3, t2;\n\t"
        "@pw sub.rn.f32x2 %7, %7, t2;\n\t"
        // c3,m3,n0: +, W, p2
        "mul.rn.f32x2 t3, %15, %16;\n\t"
        "add.rn.f32x2 %3, %3, t3;\n\t"
        "@pw add.rn.f32x2 %7, %7, t3;\n\t"
        "@p2 add.rn.f32x2 %11, %11, t3;\n\t"
        "}"
        : "+l"(gp[0]), "+l"(gp[1]), "+l"(gp[2]), "+l"(gp[3]),
          "+l"(we[0]), "+l"(we[1]), "+l"(we[2]), "+l"(we[3]),
          "+l"(in_[0]), "+l"(in_[1]), "+l"(in_[2]), "+l"(in_[3])
        : "l"(a0), "l"(a1), "l"(a2_), "l"(a3),
          "l"(b0), "l"(b1), "l"(b2_), "l"(b3),
          "r"(f));
    }

    // Cross-quad reduction: quads 1..3 park accumulators, quad 0 combines.
    if (h > 0) {
        int base = (h - 1) * 12;
#pragma unroll
        for (int q = 0; q < 4; q++) {
            red[base + q][lt]     = gp[q];
            red[base + q + 4][lt] = we[q];
            red[base + q + 8][lt] = in_[q];
        }
    }
    __syncthreads();

    if (h == 0) {
#pragma unroll
        for (int r = 0; r < 3; r++) {
#pragma unroll
            for (int q = 0; q < 4; q++) {
                ULL x0 = red[r * 12 + q][lt];
                ULL x1 = red[r * 12 + q + 4][lt];
                ULL x2 = red[r * 12 + q + 8][lt];
                asm("add.rn.f32x2 %0, %0, %1;" : "+l"(gp[q])  : "l"(x0));
                asm("add.rn.f32x2 %0, %0, %1;" : "+l"(we[q])  : "l"(x1));
                asm("add.rn.f32x2 %0, %0, %1;" : "+l"(in_[q]) : "l"(x2));
            }
        }

        float4* o4 = (float4*)out;
        {
            size_t base = (size_t)p0 * 64 + lt;
            o4[base + 0 * 1024 * 64] = make_float4(lof(gp[0]),  lof(gp[1]),  lof(gp[2]),  lof(gp[3]));
            o4[base + 1 * 1024 * 64] = make_float4(lof(we[0]),  lof(we[1]),  lof(we[2]),  lof(we[3]));
            o4[base + 2 * 1024 * 64] = make_float4(lof(in_[0]), lof(in_[1]), lof(in_[2]), lof(in_[3]));
        }
        {
            size_t base = (size_t)(p0 + 1) * 64 + lt;
            o4[base + 0 * 1024 * 64] = make_float4(hif(gp[0]),  hif(gp[1]),  hif(gp[2]),  hif(gp[3]));
            o4[base + 1 * 1024 * 64] = make_float4(hif(we[0]),  hif(we[1]),  hif(we[2]),  hif(we[3]));
            o4[base + 2 * 1024 * 64] = make_float4(hif(in_[0]), hif(in_[1]), hif(in_[2]), hif(in_[3]));
        }
    }
}

extern "C" void kernel_launch(void* const* d_in, const int* in_sizes, int n_in,
                              void* d_out, int out_size) {
    (void)in_sizes; (void)n_in; (void)out_size;
    const float* A = (const float*)d_in[0];
    const float* B = (const float*)d_in[1];
    float* out = (float*)d_out;

    build_flags_kernel<<<16, 256>>>();
    clifford_main_kernel<<<512, 256>>>(A, B, out);
}

// round 16
// speedup vs baseline: 1.5663x; 1.0979x over previous
#include <cuda_runtime.h>
#include <cstdint>

typedef unsigned long long ULL;

// Per-(jb,lt) table word:
// bit0:  S   = sign(jb, lt^jb) negative
// bit1:  W   = jb subset-of lt           (wedge outer)
// bit2:  I1  = (lt & jb)==0              (j subset k outer)
// bit3:  I2  = lt subset-of jb           (k subset j outer)
// bit4:  Ior = I1 | I2
// bit5:  P   = popc(jb) & 1              (parity cross-term)
// bits16..26: precomputed swizzled B byte offset (sLo*16)
__device__ unsigned g_flags[4096];

__global__ void build_flags_kernel() {
    int idx = blockIdx.x * blockDim.x + threadIdx.x;
    if (idx >= 4096) return;
    int lt = idx & 63;
    int jb = idx >> 6;
    int kh = lt ^ jb;
    int par = 0;
#pragma unroll
    for (int p = 0; p < 6; p++)
        if ((jb >> p) & 1) par ^= __popc(kh & ((1 << p) - 1)) & 1;
    unsigned f = (unsigned)par;
    if ((jb & ~lt) == 0) f |= 2u;    // W
    if ((lt & jb) == 0)  f |= 4u;    // I1
    if ((lt & ~jb) == 0) f |= 8u;    // I2
    if (f & 12u)         f |= 16u;   // Ior
    if (__popc(jb) & 1)  f |= 32u;   // P
    // precomputed swizzled B offset: x = lt^jb, sLo = (2x)^((x>>2)&1), bytes = sLo*16
    int x = lt ^ jb;
    unsigned off = (unsigned)((((2 * x) ^ ((x >> 2) & 1)) * 16));
    g_flags[idx] = f | (off << 16);
}

__device__ __forceinline__ float lof(ULL x) { return __uint_as_float((unsigned)x); }
__device__ __forceinline__ float hif(ULL x) { return __uint_as_float((unsigned)(x >> 32)); }

// 256 threads: 4 quads of 64. quad h handles jb in [16h,16h+16);
// lt = tid & 63 handles outputs i=4lt..4lt+3 for 2 positions packed as f32x2.
__global__ void __launch_bounds__(256) clifford_main_kernel(
    const float* __restrict__ A, const float* __restrict__ B, float* __restrict__ out)
{
    __shared__ __align__(16) float As[512];
    __shared__ __align__(16) float Bs[512];
    __shared__ ULL red[36][64];               // quads 1..3 park 12 accumulators

    const int tid = threadIdx.x;
    const int lt  = tid & 63;
    const int h   = tid >> 6;
    const int p0  = blockIdx.x * 2;
    const float* A0 = A + (size_t)p0 * 256;
    const float* B0 = B + (size_t)p0 * 256;

    // Stage A (plain) and B (16B-XOR-swizzled), pos-pair interleaved.
    {
        int n = tid;                           // 0..255
        As[2 * n]     = A0[n];
        As[2 * n + 1] = A0[n + 256];
        int u  = n >> 1;
        int s  = u ^ ((u >> 3) & 1);
        int bi = s * 4 + (n & 1) * 2;
        Bs[bi]     = B0[n];
        Bs[bi + 1] = B0[n + 256];
    }
    __syncthreads();

    ULL gp[4] = {0,0,0,0}, we[4] = {0,0,0,0}, in_[4] = {0,0,0,0};

    const ulonglong2* Asu = (const ulonglong2*)As;
    const char* Bsc = (const char*)Bs;

#pragma unroll 4
    for (int q = 0; q < 16; q++) {
        const int jb = h * 16 + q;
        const unsigned fw = __ldg(&g_flags[jb * 64 + lt]);

        // A packs for j = 4jb..4jb+3 (uniform broadcast)
        ulonglong2 aL = Asu[2 * jb];
        ulonglong2 aH = Asu[2 * jb + 1];
        ULL a0 = aL.x, a1 = aL.y, a2_ = aH.x, a3 = aH.y;

        // B packs via precomputed swizzled byte offset
        unsigned off = fw >> 16;
        ulonglong2 bL = *(const ulonglong2*)(Bsc + off);
        ulonglong2 bH = *(const ulonglong2*)(Bsc + (off ^ 16u));

        // Outer sign S; parity cross-term P flips packs n in {1,2}.
        unsigned m03 = fw << 31;
        unsigned m12 = m03 ^ ((fw << 26) & 0x80000000u);
        ULL mm03 = ((ULL)m03 << 32) | m03;
        ULL mm12 = ((ULL)m12 << 32) | m12;
        ULL b0 = bL.x ^ mm03;
        ULL b1 = bL.y ^ mm12;
        ULL b2 = bH.x ^ mm12;
        ULL b3 = bH.y ^ mm03;
        const ULL nb = 0x8000000080000000ull;   // negate both packed floats
        ULL b1n = b1 ^ nb;                       // for (m,n) pairs with negative inner sign
        ULL b3n = b3 ^ nb;

        // 39 FMAs: 16 unconditional (gp), then 23 predicated (wedge/inner),
        // ordered so accumulator chains have >=4-instr gaps and setp->@p
        // guard latency (13cyc) is hidden behind the gp block.
        asm(
        "{\n\t"
        ".reg .pred pw, p1, p2, po;\n\t"
        ".reg .b32 tf;\n\t"
        "and.b32 tf, %22, 2;  setp.ne.u32 pw, tf, 0;\n\t"
        "and.b32 tf, %22, 4;  setp.ne.u32 p1, tf, 0;\n\t"
        "and.b32 tf, %22, 8;  setp.ne.u32 p2, tf, 0;\n\t"
        "and.b32 tf, %22, 16; setp.ne.u32 po, tf, 0;\n\t"
        // gp, m0 round
        "fma.rn.f32x2 %0, %12, %16, %0;\n\t"    // c0 m0 b0
        "fma.rn.f32x2 %1, %12, %17, %1;\n\t"    // c1 m0 b1
        "fma.rn.f32x2 %2, %12, %18, %2;\n\t"    // c2 m0 b2
        "fma.rn.f32x2 %3, %12, %19, %3;\n\t"    // c3 m0 b3
        // gp, m1 round
        "fma.rn.f32x2 %0, %13, %17, %0;\n\t"    // c0 m1 b1
        "fma.rn.f32x2 %1, %13, %16, %1;\n\t"    // c1 m1 b0
        "fma.rn.f32x2 %2, %13, %19, %2;\n\t"    // c2 m1 b3
        "fma.rn.f32x2 %3, %13, %18, %3;\n\t"    // c3 m1 b2
        // gp, m2 round
        "fma.rn.f32x2 %0, %14, %18, %0;\n\t"    // c0 m2 b2
        "fma.rn.f32x2 %1, %14, %21, %1;\n\t"    // c1 m2 b3n (-)
        "fma.rn.f32x2 %2, %14, %16, %2;\n\t"    // c2 m2 b0
        "fma.rn.f32x2 %3, %14, %20, %3;\n\t"    // c3 m2 b1n (-)
        // gp, m3 round
        "fma.rn.f32x2 %0, %15, %21, %0;\n\t"    // c0 m3 b3n (-)
        "fma.rn.f32x2 %1, %15, %18, %1;\n\t"    // c1 m3 b2
        "fma.rn.f32x2 %2, %15, %20, %2;\n\t"    // c2 m3 b1n (-)
        "fma.rn.f32x2 %3, %15, %16, %3;\n\t"    // c3 m3 b0
        // predicated: wedge (9) + inner (14), acc-interleaved
        "@pw fma.rn.f32x2 %4, %12, %16, %4;\n\t"   // we0 c0m0 b0
        "@pw fma.rn.f32x2 %5, %12, %17, %5;\n\t"   // we1 c1m0 b1
        "@pw fma.rn.f32x2 %6, %12, %18, %6;\n\t"   // we2 c2m0 b2
        "@pw fma.rn.f32x2 %7, %12, %19, %7;\n\t"   // we3 c3m0 b3
        "@po fma.rn.f32x2 %8, %12, %16, %8;\n\t"   // in0 c0m0 b0
        "@p1 fma.rn.f32x2 %9, %12, %17, %9;\n\t"   // in1 c1m0 b1
        "@p1 fma.rn.f32x2 %10, %12, %18, %10;\n\t" // in2 c2m0 b2
        "@p1 fma.rn.f32x2 %11, %12, %19, %11;\n\t" // in3 c3m0 b3
        "@pw fma.rn.f32x2 %5, %13, %16, %5;\n\t"   // we1 c1m1 b0
        "@pw fma.rn.f32x2 %6, %14, %16, %6;\n\t"   // we2 c2m2 b0
        "@pw fma.rn.f32x2 %7, %13, %18, %7;\n\t"   // we3 c3m1 b2
        "@po fma.rn.f32x2 %8, %13, %17, %8;\n\t"   // in0 c0m1 b1
        "@p1 fma.rn.f32x2 %9, %14, %21, %9;\n\t"   // in1 c1m2 b3n (-)
        "@p1 fma.rn.f32x2 %10, %13, %19, %10;\n\t" // in2 c2m1 b3
        "@p2 fma.rn.f32x2 %11, %15, %16, %11;\n\t" // in3 c3m3 b0
        "@pw fma.rn.f32x2 %7, %14, %20, %7;\n\t"   // we3 c3m2 b1n (-)
        "@po fma.rn.f32x2 %8, %14, %18, %8;\n\t"   // in0 c0m2 b2
        "@p2 fma.rn.f32x2 %9, %13, %16, %9;\n\t"   // in1 c1m1 b0
        "@p2 fma.rn.f32x2 %10, %14, %16, %10;\n\t" // in2 c2m2 b0
        "@pw fma.rn.f32x2 %7, %15, %16, %7;\n\t"   // we3 c3m3 b0
        "@po fma.rn.f32x2 %8, %15, %21, %8;\n\t"   // in0 c0m3 b3n (-)
        "@p2 fma.rn.f32x2 %9, %15, %18, %9;\n\t"   // in1 c1m3 b2
        "@p2 fma.rn.f32x2 %10, %15, %20, %10;\n\t" // in2 c2m3 b1n (-)
        "}"
        : "+l"(gp[0]), "+l"(gp[1]), "+l"(gp[2]), "+l"(gp[3]),
          "+l"(we[0]), "+l"(we[1]), "+l"(we[2]), "+l"(we[3]),
          "+l"(in_[0]), "+l"(in_[1]), "+l"(in_[2]), "+l"(in_[3])
        : "l"(a0), "l"(a1), "l"(a2_), "l"(a3),
          "l"(b0), "l"(b1), "l"(b2), "l"(b3),
          "l"(b1n), "l"(b3n),
          "r"(fw));
    }

    // Cross-quad reduction: quads 1..3 park accumulators, quad 0 combines.
    if (h > 0) {
        int base = (h - 1) * 12;
#pragma unroll
        for (int q = 0; q < 4; q++) {
            red[base + q][lt]     = gp[q];
            red[base + q + 4][lt] = we[q];
            red[base + q + 8][lt] = in_[q];
        }
    }
    __syncthreads();

    if (h == 0) {
#pragma unroll
        for (int r = 0; r < 3; r++) {
#pragma unroll
            for (int q = 0; q < 4; q++) {
                ULL x0 = red[r * 12 + q][lt];
                ULL x1 = red[r * 12 + q + 4][lt];
                ULL x2 = red[r * 12 + q + 8][lt];
                asm("add.rn.f32x2 %0, %0, %1;" : "+l"(gp[q])  : "l"(x0));
                asm("add.rn.f32x2 %0, %0, %1;" : "+l"(we[q])  : "l"(x1));
                asm("add.rn.f32x2 %0, %0, %1;" : "+l"(in_[q]) : "l"(x2));
            }
        }

        float4* o4 = (float4*)out;
        {
            size_t base = (size_t)p0 * 64 + lt;
            o4[base + 0 * 1024 * 64] = make_float4(lof(gp[0]),  lof(gp[1]),  lof(gp[2]),  lof(gp[3]));
            o4[base + 1 * 1024 * 64] = make_float4(lof(we[0]),  lof(we[1]),  lof(we[2]),  lof(we[3]));
            o4[base + 2 * 1024 * 64] = make_float4(lof(in_[0]), lof(in_[1]), lof(in_[2]), lof(in_[3]));
        }
        {
            size_t base = (size_t)(p0 + 1) * 64 + lt;
            o4[base + 0 * 1024 * 64] = make_float4(hif(gp[0]),  hif(gp[1]),  hif(gp[2]),  hif(gp[3]));
            o4[base + 1 * 1024 * 64] = make_float4(hif(we[0]),  hif(we[1]),  hif(we[2]),  hif(we[3]));
            o4[base + 2 * 1024 * 64] = make_float4(hif(in_[0]), hif(in_[1]), hif(in_[2]), hif(in_[3]));
        }
    }
}

extern "C" void kernel_launch(void* const* d_in, const int* in_sizes, int n_in,
                              void* d_out, int out_size) {
    (void)in_sizes; (void)n_in; (void)out_size;
    const float* A = (const float*)d_in[0];
    const float* B = (const float*)d_in[1];
    float* out = (float*)d_out;

    build_flags_kernel<<<16, 256>>>();
    clifford_main_kernel<<<512, 256>>>(A, B, out);
}